// round 13
// baseline (speedup 1.0000x reference)
#include <cuda_runtime.h>
#include <cuda_fp16.h>
#include <cstdint>

#define B_   2
#define SQ_  1024
#define SKV_ 2048
#define E_   1024
#define H_   16
#define VOC_ 4096
#define KDIM 1024

// ---------------------------------------------------------------------------
// Static scratch
// ---------------------------------------------------------------------------
__device__ __half g_Qh [B_*SQ_ *E_];
__device__ __half g_Kh [B_*SKV_*E_];
__device__ __half g_Vh [B_*SKV_*E_];
__device__ __half g_AOh[B_*SQ_ *E_];
__device__ __half g_xh [B_*SQ_ *E_];
__device__ __half g_ch [B_*SKV_*E_];
__device__ __half g_Wqh[E_*E_];
__device__ __half g_Wkh[E_*E_];
__device__ __half g_Wvh[E_*E_];
__device__ __half g_Wph[(size_t)E_*VOC_];

// ---------------------------------------------------------------------------
// PTX helpers (baseline PTX only — compiles for compute_103)
// ---------------------------------------------------------------------------
__device__ __forceinline__ uint32_t smem_u32(const void* p) {
    uint32_t a;
    asm("{ .reg .u64 t; cvta.to.shared.u64 t, %1; cvt.u32.u64 %0, t; }"
        : "=r"(a) : "l"(p));
    return a;
}

#define CP16(s, g) \
    asm volatile("cp.async.cg.shared.global [%0], [%1], 16;" :: "r"(s), "l"(g))
#define CP_COMMIT() asm volatile("cp.async.commit_group;" ::: "memory")
#define CP_WAIT0()  asm volatile("cp.async.wait_group 0;" ::: "memory")
#define CP_WAIT1()  asm volatile("cp.async.wait_group 1;" ::: "memory")

#define LDSM4(d0, d1, d2, d3, a)                                              \
    asm volatile("ldmatrix.sync.aligned.m8n8.x4.shared.b16 {%0,%1,%2,%3}, [%4];" \
        : "=r"(d0), "=r"(d1), "=r"(d2), "=r"(d3) : "r"(a))
#define LDSM4T(d0, d1, d2, d3, a)                                             \
    asm volatile("ldmatrix.sync.aligned.m8n8.x4.trans.shared.b16 {%0,%1,%2,%3}, [%4];" \
        : "=r"(d0), "=r"(d1), "=r"(d2), "=r"(d3) : "r"(a))

#define MMA16816(c, a, b0, b1)                                                \
    asm volatile("mma.sync.aligned.m16n8k16.row.col.f32.f16.f16.f32 "         \
        "{%0,%1,%2,%3},{%4,%5,%6,%7},{%8,%9},{%0,%1,%2,%3};"                  \
        : "+f"((c)[0]), "+f"((c)[1]), "+f"((c)[2]), "+f"((c)[3])              \
        : "r"((a)[0]), "r"((a)[1]), "r"((a)[2]), "r"((a)[3]), "r"(b0), "r"(b1))

__device__ __forceinline__ uint32_t packh2(float x, float y) {
    __half2 h = __floats2half2_rn(x, y);
    return *reinterpret_cast<uint32_t*>(&h);
}

// ---------------------------------------------------------------------------
// Fused fp32 -> fp16 conversion for ALL tensors in ONE launch.
// ---------------------------------------------------------------------------
#define F2H_BLOCKS 13312

__global__ __launch_bounds__(256)
void f2h_all(const float* __restrict__ x,   const float* __restrict__ ctx,
             const float* __restrict__ wq,  const float* __restrict__ wk,
             const float* __restrict__ wv,  const float* __restrict__ wp,
             __half* xh, __half* ch, __half* wqh,
             __half* wkh, __half* wvh, __half* wph)
{
    const int bb = blockIdx.x;
    const float* in; __half* out; int base;
    if      (bb < 2048) { in = x;   out = xh;  base = bb;        }
    else if (bb < 6144) { in = ctx; out = ch;  base = bb - 2048; }
    else if (bb < 7168) { in = wq;  out = wqh; base = bb - 6144; }
    else if (bb < 8192) { in = wk;  out = wkh; base = bb - 7168; }
    else if (bb < 9216) { in = wv;  out = wvh; base = bb - 8192; }
    else                { in = wp;  out = wph; base = bb - 9216; }
    const size_t i = (size_t)base * 1024 + threadIdx.x * 4;
    float4 v = *(const float4*)(in + i);
    *(__half2*)(out + i)     = __floats2half2_rn(v.x, v.y);
    *(__half2*)(out + i + 2) = __floats2half2_rn(v.z, v.w);
}

// ---------------------------------------------------------------------------
// fp16 tensor-core GEMM body: 128x128x32 CTA tile, 128 threads / 4 warps in
// 2x2 grid, warp tile 64x64, 3-stage cp.async, one sync per K-iteration.
// Warps traverse (ks, np) in warp-dependent order so LDSM and MMA phases of
// different warps interleave (crossbar/tensor overlap).
// ---------------------------------------------------------------------------
#define GS   40          // A smem row stride (halves): 32 + 8 pad = 80B
#define BSS  136         // B smem row stride (halves): 128 + 8 pad = 272B
#define A_STG (128 * GS * 2)
#define B_STG (32 * BSS * 2)
#define GEMM_SMEM (3 * (A_STG + B_STG))
#define GT 128           // threads per GEMM CTA

__device__ __forceinline__
void gemm_body(const __half* __restrict__ A, const __half* __restrict__ W,
               const float* __restrict__ bias, float* __restrict__ Cf,
               __half* __restrict__ Ch, int N, int K,
               int rowBase, int colBase, char* gsm)
{
    __half* As = (__half*)gsm;
    __half* Bs = (__half*)(gsm + 3 * A_STG);

    const int tid = threadIdx.x;
    const int lane = tid & 31, wid = tid >> 5;
    const int wm = wid & 1, wn = wid >> 1;        // 2x2 warp grid, 64x64 tiles
    const int ksRev = wid & 1;                    // stagger: ks order by warp
    const int npRev = (wid >> 1) & 1;             // stagger: np order by warp

    const __half* Aga[4]; uint32_t sAa[4];
#pragma unroll
    for (int i = 0; i < 4; i++) {
        const int idx = tid + i * GT;
        const int row = idx >> 2, seg = idx & 3;
        Aga[i] = A + (size_t)(rowBase + row) * K + seg * 8;
        sAa[i] = smem_u32(As + row * GS + seg * 8);
    }
    const __half* Bga[4]; uint32_t sBa[4];
#pragma unroll
    for (int i = 0; i < 4; i++) {
        const int idx = tid + i * GT;
        const int row = idx >> 4, seg = idx & 15;
        Bga[i] = W + (size_t)row * N + colBase + seg * 8;
        sBa[i] = smem_u32(Bs + row * BSS + seg * 8);
    }

    auto issue = [&](int st, int it) {
        const int kk = it * 32;
        const size_t koff = (size_t)kk * N;
#pragma unroll
        for (int i = 0; i < 4; i++) {
            CP16(sAa[i] + st * A_STG, Aga[i] + kk);
            CP16(sBa[i] + st * B_STG, Bga[i] + koff);
        }
        CP_COMMIT();
    };

    const uint32_t aAddr = smem_u32(As + (wm * 64 + (lane & 15)) * GS + (lane >> 4) * 8);
    const int g = lane >> 3;
    const uint32_t bAddr = smem_u32(Bs + ((g & 1) * 8 + (lane & 7)) * BSS
                                       + wn * 64 + (g >> 1) * 8);

    float acc[4][8][4];
#pragma unroll
    for (int i = 0; i < 4; i++)
#pragma unroll
        for (int j = 0; j < 8; j++)
#pragma unroll
            for (int q = 0; q < 4; q++) acc[i][j][q] = 0.f;

    issue(0, 0);
    issue(1, 1);

    const int NIT = K >> 5;
    int st = 0, st2 = 2;
    for (int it = 0; it < NIT; it++) {
        if (it < NIT - 1) CP_WAIT1(); else CP_WAIT0();
        __syncthreads();

        const uint32_t ao = st * A_STG, bo = st * B_STG;
#pragma unroll
        for (int kss = 0; kss < 2; kss++) {
            const int ks = ksRev ? 1 - kss : kss;
            uint32_t a[4][4];
#pragma unroll
            for (int mt = 0; mt < 4; mt++)
                LDSM4(a[mt][0], a[mt][1], a[mt][2], a[mt][3],
                      aAddr + ao + (mt * 16 * GS + ks * 16) * 2);
#pragma unroll
            for (int nps = 0; nps < 4; nps++) {
                const int np = npRev ? 3 - nps : nps;
                uint32_t d0, d1, d2, d3;
                LDSM4T(d0, d1, d2, d3,
                       bAddr + bo + (ks * 16 * BSS + np * 16) * 2);
#pragma unroll
                for (int mt = 0; mt < 4; mt++) {
                    MMA16816(acc[mt][np * 2],     a[mt], d0, d1);
                    MMA16816(acc[mt][np * 2 + 1], a[mt], d2, d3);
                }
            }
        }

        if (it + 2 < NIT) issue(st2, it + 2);
        st  = (st  == 2) ? 0 : st  + 1;
        st2 = (st2 == 2) ? 0 : st2 + 1;
    }

    const int r0 = rowBase + wm * 64 + (lane >> 2);
    const int c0 = colBase + wn * 64 + (lane & 3) * 2;
#pragma unroll
    for (int mt = 0; mt < 4; mt++)
#pragma unroll
        for (int nt = 0; nt < 8; nt++) {
            const int c = c0 + nt * 8;
            const float bx = bias[c], by = bias[c + 1];
#pragma unroll
            for (int rr = 0; rr < 2; rr++) {
                const int r = r0 + mt * 16 + rr * 8;
                const float vx = acc[mt][nt][rr * 2]     + bx;
                const float vy = acc[mt][nt][rr * 2 + 1] + by;
                if (Cf) {
                    float2 o; o.x = vx; o.y = vy;
                    *(float2*)(Cf + (size_t)r * N + c) = o;
                } else {
                    *(__half2*)(Ch + (size_t)r * N + c) = __floats2half2_rn(vx, vy);
                }
            }
        }
}

// Merged QKV projection, flattened grid: y in [0,80) selects op + row tile.
__global__ __launch_bounds__(GT, 2)
void gemm_qkv(const __half* __restrict__ xh, const __half* __restrict__ ch,
              const __half* __restrict__ wq, const __half* __restrict__ wk,
              const __half* __restrict__ wv,
              const float* __restrict__ bq, const float* __restrict__ bk,
              const float* __restrict__ bv,
              __half* __restrict__ Qh, __half* __restrict__ Kh,
              __half* __restrict__ Vh)
{
    extern __shared__ __align__(16) char gsm[];
    const int y = blockIdx.y;
    const __half* A; const __half* W; const float* bias; __half* C; int rowBase;
    if (y < 16)      { A = xh; W = wq; bias = bq; C = Qh; rowBase = y * 128; }
    else if (y < 48) { A = ch; W = wk; bias = bk; C = Kh; rowBase = (y - 16) * 128; }
    else             { A = ch; W = wv; bias = bv; C = Vh; rowBase = (y - 48) * 128; }
    gemm_body(A, W, bias, nullptr, C, E_, KDIM, rowBase, blockIdx.x * 128, gsm);
}

// Vocab projection (fp32 out).
__global__ __launch_bounds__(GT, 2)
void gemm_vocab(const __half* __restrict__ A, const __half* __restrict__ W,
                const float* __restrict__ bias, float* __restrict__ C)
{
    extern __shared__ __align__(16) char gsm[];
    gemm_body(A, W, bias, C, nullptr, VOC_, KDIM,
              blockIdx.y * 128, blockIdx.x * 128, gsm);
}

// ---------------------------------------------------------------------------
// fp16 flash attention (round-11 version): CTA = (128-q tile, head, batch),
// 128 thr / 4 warps, warp q-tile 32, Q fragments hoisted, 3-stage pipeline.
// ---------------------------------------------------------------------------
#define AS 72   // attention smem row stride in halves (64 + 8 pad = 144B)
#define ATTN_SMEM ((128 * AS + 6 * 64 * AS) * 2)
#define AT 128  // threads per attention CTA

__global__ __launch_bounds__(AT)
void attn_h(const __half* __restrict__ Q, const __half* __restrict__ K,
            const __half* __restrict__ V, __half* __restrict__ O)
{
    extern __shared__ __align__(16) __half sh[];
    __half* Qs = sh;                       // 128*72
    __half* Ks = sh + 128 * AS;            // 3 stages of 64*72
    __half* Vs = Ks + 3 * 64 * AS;         // 3 stages of 64*72

    const int tid = threadIdx.x, lane = tid & 31, wid = tid >> 5;
    const int qt = blockIdx.x, h = blockIdx.y, b = blockIdx.z;

    const __half* Qg = Q + ((size_t)b * SQ_ + qt * 128) * E_ + h * 64;
#pragma unroll
    for (int i = 0; i < 8; i++) {
        int idx = tid + i * AT;            // 0..1023
        int row = idx >> 3, seg = idx & 7;
        *(uint4*)(Qs + row * AS + seg * 8) =
            *(const uint4*)(Qg + (size_t)row * E_ + seg * 8);
    }

    const __half* Kg0 = K + (size_t)b * SKV_ * E_ + h * 64;
    const __half* Vg0 = V + (size_t)b * SKV_ * E_ + h * 64;
    const uint32_t ksb = smem_u32(Ks), vsb = smem_u32(Vs);
    const uint32_t KSTG = 64 * AS * 2;

    auto issue = [&](int st, int c) {
        const __half* Kg = Kg0 + (size_t)c * 64 * E_;
        const __half* Vg = Vg0 + (size_t)c * 64 * E_;
#pragma unroll
        for (int i = 0; i < 4; i++) {
            int idx = tid + i * AT;        // 0..511
            int row = idx >> 3, seg = idx & 7;
            uint32_t so = st * KSTG + (row * AS + seg * 8) * 2;
            CP16(ksb + so, Kg + (size_t)row * E_ + seg * 8);
            CP16(vsb + so, Vg + (size_t)row * E_ + seg * 8);
        }
        CP_COMMIT();
    };

    issue(0, 0);
    issue(1, 1);
    __syncthreads();                        // Q smem visible to all warps

    // Hoist Q fragments: warp owns q rows wid*32 .. wid*32+31 (2 m-tiles)
    uint32_t qf[4][2][4];                   // [ks][mt]
    {
        const uint32_t qA = smem_u32(Qs + (wid * 32 + (lane & 15)) * AS + (lane >> 4) * 8);
#pragma unroll
        for (int ks = 0; ks < 4; ks++)
#pragma unroll
            for (int mt = 0; mt < 2; mt++)
                LDSM4(qf[ks][mt][0], qf[ks][mt][1], qf[ks][mt][2], qf[ks][mt][3],
                      qA + (mt * 16 * AS + ks * 16) * 2);
    }

    float m2[4] = { -1e30f, -1e30f, -1e30f, -1e30f };
    float ls[4] = { 0.f, 0.f, 0.f, 0.f };
    float o[2][8][4];
#pragma unroll
    for (int mt = 0; mt < 2; mt++)
#pragma unroll
        for (int i = 0; i < 8; i++)
#pragma unroll
            for (int j = 0; j < 4; j++) o[mt][i][j] = 0.f;

    const float c2 = 0.125f * 1.44269504089f;   // scale * log2(e)
    const int NKV = SKV_ / 64;

    int st = 0, st2 = 2;
    for (int c = 0; c < NKV; c++) {
        if (c < NKV - 1) CP_WAIT1(); else CP_WAIT0();
        __syncthreads();
        const uint32_t so = st * KSTG;

        // ---- S = Q @ K^T  (32 x 64 per warp); each K ldmatrix feeds 4 MMAs
        float sacc[2][8][4];
#pragma unroll
        for (int mt = 0; mt < 2; mt++)
#pragma unroll
            for (int i = 0; i < 8; i++)
#pragma unroll
                for (int j = 0; j < 4; j++) sacc[mt][i][j] = 0.f;

#pragma unroll
        for (int ks = 0; ks < 4; ks++)
#pragma unroll
            for (int np = 0; np < 4; np++) {
                uint32_t d0, d1, d2, d3;
                LDSM4(d0, d1, d2, d3,
                      ksb + so + ((np * 16 + (lane & 15)) * AS + ks * 16 + (lane >> 4) * 8) * 2);
                MMA16816(sacc[0][np * 2],     qf[ks][0], d0, d2);
                MMA16816(sacc[0][np * 2 + 1], qf[ks][0], d1, d3);
                MMA16816(sacc[1][np * 2],     qf[ks][1], d0, d2);
                MMA16816(sacc[1][np * 2 + 1], qf[ks][1], d1, d3);
            }

        // ---- online softmax (base-2); 4 row groups: idx = mt*2 + rr
#pragma unroll
        for (int mt = 0; mt < 2; mt++)
#pragma unroll
            for (int i = 0; i < 8; i++)
#pragma unroll
                for (int j = 0; j < 4; j++) sacc[mt][i][j] *= c2;

#pragma unroll
        for (int idx = 0; idx < 4; idx++) {
            const int mt = idx >> 1, rh = idx & 1;
            float mx = -1e30f;
#pragma unroll
            for (int nt = 0; nt < 8; nt++)
                mx = fmaxf(mx, fmaxf(sacc[mt][nt][rh * 2], sacc[mt][nt][rh * 2 + 1]));
            mx = fmaxf(mx, __shfl_xor_sync(0xffffffffu, mx, 1));
            mx = fmaxf(mx, __shfl_xor_sync(0xffffffffu, mx, 2));
            const float mn = fmaxf(m2[idx], mx);
            const float al = exp2f(m2[idx] - mn);
            float rs = 0.f;
#pragma unroll
            for (int nt = 0; nt < 8; nt++) {
                sacc[mt][nt][rh * 2]     = exp2f(sacc[mt][nt][rh * 2]     - mn);
                sacc[mt][nt][rh * 2 + 1] = exp2f(sacc[mt][nt][rh * 2 + 1] - mn);
                rs += sacc[mt][nt][rh * 2] + sacc[mt][nt][rh * 2 + 1];
            }
            rs += __shfl_xor_sync(0xffffffffu, rs, 1);
            rs += __shfl_xor_sync(0xffffffffu, rs, 2);
            ls[idx] = ls[idx] * al + rs;
            m2[idx] = mn;
#pragma unroll
            for (int nt = 0; nt < 8; nt++) {
                o[mt][nt][rh * 2]     *= al;
                o[mt][nt][rh * 2 + 1] *= al;
            }
        }

        // ---- O += P @ V ; each V ldmatrix feeds 4 MMAs
        const int g = lane >> 3;
#pragma unroll
        for (int t = 0; t < 4; t++) {
            uint32_t pa[2][4];
#pragma unroll
            for (int mt = 0; mt < 2; mt++) {
                pa[mt][0] = packh2(sacc[mt][2 * t][0],     sacc[mt][2 * t][1]);
                pa[mt][1] = packh2(sacc[mt][2 * t][2],     sacc[mt][2 * t][3]);
                pa[mt][2] = packh2(sacc[mt][2 * t + 1][0], sacc[mt][2 * t + 1][1]);
                pa[mt][3] = packh2(sacc[mt][2 * t + 1][2], sacc[mt][2 * t + 1][3]);
            }
#pragma unroll
            for (int np = 0; np < 4; np++) {
                uint32_t d0, d1, d2, d3;
                uint32_t va = vsb + so +
                    ((t * 16 + (g & 1) * 8 + (lane & 7)) * AS + np * 16 + (g >> 1) * 8) * 2;
                LDSM4T(d0, d1, d2, d3, va);
                MMA16816(o[0][np * 2],     pa[0], d0, d1);
                MMA16816(o[0][np * 2 + 1], pa[0], d2, d3);
                MMA16816(o[1][np * 2],     pa[1], d0, d1);
                MMA16816(o[1][np * 2 + 1], pa[1], d2, d3);
            }
        }

        if (c + 2 < NKV) issue(st2, c + 2);
        st  = (st  == 2) ? 0 : st  + 1;
        st2 = (st2 == 2) ? 0 : st2 + 1;
    }

    // ---- epilogue: normalize, fp16 store
#pragma unroll
    for (int mt = 0; mt < 2; mt++)
#pragma unroll
        for (int rr = 0; rr < 2; rr++) {
            const float inv = 1.f / ls[mt * 2 + rr];
            const int row = qt * 128 + wid * 32 + mt * 16 + rr * 8 + (lane >> 2);
            const size_t base = ((size_t)b * SQ_ + row) * E_ + h * 64 + (lane & 3) * 2;
#pragma unroll
            for (int nt = 0; nt < 8; nt++)
                *(__half2*)(O + base + nt * 8) =
                    __floats2half2_rn(o[mt][nt][rr * 2] * inv, o[mt][nt][rr * 2 + 1] * inv);
        }
}

// ---------------------------------------------------------------------------
// Launch
// ---------------------------------------------------------------------------
extern "C" void kernel_launch(void* const* d_in, const int* in_sizes, int n_in,
                              void* d_out, int out_size)
{
    (void)in_sizes; (void)n_in; (void)out_size;
    const float* x   = (const float*)d_in[0];
    const float* ctx = (const float*)d_in[1];
    const float* Wq  = (const float*)d_in[2];
    const float* bq  = (const float*)d_in[3];
    const float* Wk  = (const float*)d_in[4];
    const float* bk  = (const float*)d_in[5];
    const float* Wv  = (const float*)d_in[6];
    const float* bv  = (const float*)d_in[7];
    const float* Wp  = (const float*)d_in[8];
    const float* bp  = (const float*)d_in[9];
    float* out = (float*)d_out;

    __half *Qh, *Kh, *Vh, *AOh, *xh, *ch, *wq, *wk, *wv, *wp;
    cudaGetSymbolAddress((void**)&Qh,  g_Qh);
    cudaGetSymbolAddress((void**)&Kh,  g_Kh);
    cudaGetSymbolAddress((void**)&Vh,  g_Vh);
    cudaGetSymbolAddress((void**)&AOh, g_AOh);
    cudaGetSymbolAddress((void**)&xh,  g_xh);
    cudaGetSymbolAddress((void**)&ch,  g_ch);
    cudaGetSymbolAddress((void**)&wq,  g_Wqh);
    cudaGetSymbolAddress((void**)&wk,  g_Wkh);
    cudaGetSymbolAddress((void**)&wv,  g_Wvh);
    cudaGetSymbolAddress((void**)&wp,  g_Wph);

    cudaFuncSetAttribute(attn_h,    cudaFuncAttributeMaxDynamicSharedMemorySize, ATTN_SMEM);
    cudaFuncSetAttribute(gemm_qkv,  cudaFuncAttributeMaxDynamicSharedMemorySize, GEMM_SMEM);
    cudaFuncSetAttribute(gemm_vocab,cudaFuncAttributeMaxDynamicSharedMemorySize, GEMM_SMEM);

    // all fp32 -> fp16 conversions, one launch
    f2h_all<<<F2H_BLOCKS, 256>>>(x, ctx, Wq, Wk, Wv, Wp,
                                 xh, ch, wq, wk, wv, wp);

    // QKV projections, one launch, flattened exact grid (640 CTAs)
    gemm_qkv<<<dim3(E_ / 128, 80), GT, GEMM_SMEM>>>(
        xh, ch, wq, wk, wv, bq, bk, bv, Qh, Kh, Vh);

    // attention (fp16 in/out)
    attn_h<<<dim3(SQ_ / 128, H_, B_), AT, ATTN_SMEM>>>(Qh, Kh, Vh, AOh);

    // vocab projection (fp32 out)
    gemm_vocab<<<dim3(VOC_ / 128, (B_ * SQ_) / 128), GT, GEMM_SMEM>>>(AOh, wp, bp, out);
}

// round 14
// speedup vs baseline: 4.3407x; 4.3407x over previous
#include <cuda_runtime.h>
#include <cuda_fp16.h>
#include <cstdint>

#define B_   2
#define SQ_  1024
#define SKV_ 2048
#define E_   1024
#define H_   16
#define VOC_ 4096
#define KDIM 1024

// ---------------------------------------------------------------------------
// Static scratch
// ---------------------------------------------------------------------------
__device__ __half g_Qh [B_*SQ_ *E_];
__device__ __half g_Kh [B_*SKV_*E_];
__device__ __half g_Vh [B_*SKV_*E_];
__device__ __half g_AOh[B_*SQ_ *E_];
__device__ __half g_xh [B_*SQ_ *E_];
__device__ __half g_ch [B_*SKV_*E_];
__device__ __half g_Wqh[E_*E_];
__device__ __half g_Wkh[E_*E_];
__device__ __half g_Wvh[E_*E_];
__device__ __half g_Wph[(size_t)E_*VOC_];

// ---------------------------------------------------------------------------
// PTX helpers (baseline PTX only — compiles for compute_103)
// ---------------------------------------------------------------------------
__device__ __forceinline__ uint32_t smem_u32(const void* p) {
    uint32_t a;
    asm("{ .reg .u64 t; cvta.to.shared.u64 t, %1; cvt.u32.u64 %0, t; }"
        : "=r"(a) : "l"(p));
    return a;
}

#define CP16(s, g) \
    asm volatile("cp.async.cg.shared.global [%0], [%1], 16;" :: "r"(s), "l"(g))
#define CP_COMMIT() asm volatile("cp.async.commit_group;" ::: "memory")
#define CP_WAIT0()  asm volatile("cp.async.wait_group 0;" ::: "memory")
#define CP_WAIT1()  asm volatile("cp.async.wait_group 1;" ::: "memory")

#define LDSM4(d0, d1, d2, d3, a)                                              \
    asm volatile("ldmatrix.sync.aligned.m8n8.x4.shared.b16 {%0,%1,%2,%3}, [%4];" \
        : "=r"(d0), "=r"(d1), "=r"(d2), "=r"(d3) : "r"(a))
#define LDSM4T(d0, d1, d2, d3, a)                                             \
    asm volatile("ldmatrix.sync.aligned.m8n8.x4.trans.shared.b16 {%0,%1,%2,%3}, [%4];" \
        : "=r"(d0), "=r"(d1), "=r"(d2), "=r"(d3) : "r"(a))

#define MMA16816(c, a, b0, b1)                                                \
    asm volatile("mma.sync.aligned.m16n8k16.row.col.f32.f16.f16.f32 "         \
        "{%0,%1,%2,%3},{%4,%5,%6,%7},{%8,%9},{%0,%1,%2,%3};"                  \
        : "+f"((c)[0]), "+f"((c)[1]), "+f"((c)[2]), "+f"((c)[3])              \
        : "r"((a)[0]), "r"((a)[1]), "r"((a)[2]), "r"((a)[3]), "r"(b0), "r"(b1))

__device__ __forceinline__ uint32_t packh2(float x, float y) {
    __half2 h = __floats2half2_rn(x, y);
    return *reinterpret_cast<uint32_t*>(&h);
}

// ---------------------------------------------------------------------------
// Fused fp32 -> fp16 conversion for ALL tensors in ONE launch.
// ---------------------------------------------------------------------------
#define F2H_BLOCKS 13312

__global__ __launch_bounds__(256)
void f2h_all(const float* __restrict__ x,   const float* __restrict__ ctx,
             const float* __restrict__ wq,  const float* __restrict__ wk,
             const float* __restrict__ wv,  const float* __restrict__ wp,
             __half* xh, __half* ch, __half* wqh,
             __half* wkh, __half* wvh, __half* wph)
{
    const int bb = blockIdx.x;
    const float* in; __half* out; int base;
    if      (bb < 2048) { in = x;   out = xh;  base = bb;        }
    else if (bb < 6144) { in = ctx; out = ch;  base = bb - 2048; }
    else if (bb < 7168) { in = wq;  out = wqh; base = bb - 6144; }
    else if (bb < 8192) { in = wk;  out = wkh; base = bb - 7168; }
    else if (bb < 9216) { in = wv;  out = wvh; base = bb - 8192; }
    else                { in = wp;  out = wph; base = bb - 9216; }
    const size_t i = (size_t)base * 1024 + threadIdx.x * 4;
    float4 v = *(const float4*)(in + i);
    *(__half2*)(out + i)     = __floats2half2_rn(v.x, v.y);
    *(__half2*)(out + i + 2) = __floats2half2_rn(v.z, v.w);
}

// ---------------------------------------------------------------------------
// fp16 tensor-core GEMM body (EXACT round-11 version — known good):
// 128x128x32 CTA tile, 128 threads / 4 warps in 2x2 grid, warp tile 64x64,
// 3-stage cp.async, one sync per K-iteration, compile-time traversal order.
// ---------------------------------------------------------------------------
#define GS   40          // A smem row stride (halves): 32 + 8 pad = 80B
#define BSS  136         // B smem row stride (halves): 128 + 8 pad = 272B
#define A_STG (128 * GS * 2)
#define B_STG (32 * BSS * 2)
#define GEMM_SMEM (3 * (A_STG + B_STG))
#define GT 128           // threads per GEMM CTA

__device__ __forceinline__
void gemm_body(const __half* __restrict__ A, const __half* __restrict__ W,
               const float* __restrict__ bias, float* __restrict__ Cf,
               __half* __restrict__ Ch, int N, int K,
               int rowBase, int colBase, char* gsm)
{
    __half* As = (__half*)gsm;
    __half* Bs = (__half*)(gsm + 3 * A_STG);

    const int tid = threadIdx.x;
    const int lane = tid & 31, wid = tid >> 5;
    const int wm = wid & 1, wn = wid >> 1;        // 2x2 warp grid, 64x64 tiles

    const __half* Aga[4]; uint32_t sAa[4];
#pragma unroll
    for (int i = 0; i < 4; i++) {
        const int idx = tid + i * GT;
        const int row = idx >> 2, seg = idx & 3;
        Aga[i] = A + (size_t)(rowBase + row) * K + seg * 8;
        sAa[i] = smem_u32(As + row * GS + seg * 8);
    }
    const __half* Bga[4]; uint32_t sBa[4];
#pragma unroll
    for (int i = 0; i < 4; i++) {
        const int idx = tid + i * GT;
        const int row = idx >> 4, seg = idx & 15;
        Bga[i] = W + (size_t)row * N + colBase + seg * 8;
        sBa[i] = smem_u32(Bs + row * BSS + seg * 8);
    }

    auto issue = [&](int st, int it) {
        const int kk = it * 32;
        const size_t koff = (size_t)kk * N;
#pragma unroll
        for (int i = 0; i < 4; i++) {
            CP16(sAa[i] + st * A_STG, Aga[i] + kk);
            CP16(sBa[i] + st * B_STG, Bga[i] + koff);
        }
        CP_COMMIT();
    };

    const uint32_t aAddr = smem_u32(As + (wm * 64 + (lane & 15)) * GS + (lane >> 4) * 8);
    const int g = lane >> 3;
    const uint32_t bAddr = smem_u32(Bs + ((g & 1) * 8 + (lane & 7)) * BSS
                                       + wn * 64 + (g >> 1) * 8);

    float acc[4][8][4];
#pragma unroll
    for (int i = 0; i < 4; i++)
#pragma unroll
        for (int j = 0; j < 8; j++)
#pragma unroll
            for (int q = 0; q < 4; q++) acc[i][j][q] = 0.f;

    issue(0, 0);
    issue(1, 1);

    const int NIT = K >> 5;
    int st = 0, st2 = 2;
    for (int it = 0; it < NIT; it++) {
        if (it < NIT - 1) CP_WAIT1(); else CP_WAIT0();
        __syncthreads();

        const uint32_t ao = st * A_STG, bo = st * B_STG;
#pragma unroll
        for (int ks = 0; ks < 2; ks++) {
            uint32_t a[4][4];
#pragma unroll
            for (int mt = 0; mt < 4; mt++)
                LDSM4(a[mt][0], a[mt][1], a[mt][2], a[mt][3],
                      aAddr + ao + (mt * 16 * GS + ks * 16) * 2);
#pragma unroll
            for (int np = 0; np < 4; np++) {
                uint32_t d0, d1, d2, d3;
                LDSM4T(d0, d1, d2, d3,
                       bAddr + bo + (ks * 16 * BSS + np * 16) * 2);
#pragma unroll
                for (int mt = 0; mt < 4; mt++) {
                    MMA16816(acc[mt][np * 2],     a[mt], d0, d1);
                    MMA16816(acc[mt][np * 2 + 1], a[mt], d2, d3);
                }
            }
        }

        if (it + 2 < NIT) issue(st2, it + 2);
        st  = (st  == 2) ? 0 : st  + 1;
        st2 = (st2 == 2) ? 0 : st2 + 1;
    }

    const int r0 = rowBase + wm * 64 + (lane >> 2);
    const int c0 = colBase + wn * 64 + (lane & 3) * 2;
#pragma unroll
    for (int mt = 0; mt < 4; mt++)
#pragma unroll
        for (int nt = 0; nt < 8; nt++) {
            const int c = c0 + nt * 8;
            const float bx = bias[c], by = bias[c + 1];
#pragma unroll
            for (int rr = 0; rr < 2; rr++) {
                const int r = r0 + mt * 16 + rr * 8;
                const float vx = acc[mt][nt][rr * 2]     + bx;
                const float vy = acc[mt][nt][rr * 2 + 1] + by;
                if (Cf) {
                    float2 o; o.x = vx; o.y = vy;
                    *(float2*)(Cf + (size_t)r * N + c) = o;
                } else {
                    *(__half2*)(Ch + (size_t)r * N + c) = __floats2half2_rn(vx, vy);
                }
            }
        }
}

// Merged QKV projection, flattened grid: y in [0,80) selects op + row tile.
__global__ __launch_bounds__(GT, 2)
void gemm_qkv(const __half* __restrict__ xh, const __half* __restrict__ ch,
              const __half* __restrict__ wq, const __half* __restrict__ wk,
              const __half* __restrict__ wv,
              const float* __restrict__ bq, const float* __restrict__ bk,
              const float* __restrict__ bv,
              __half* __restrict__ Qh, __half* __restrict__ Kh,
              __half* __restrict__ Vh)
{
    extern __shared__ __align__(16) char gsm[];
    const int y = blockIdx.y;
    const __half* A; const __half* W; const float* bias; __half* C; int rowBase;
    if (y < 16)      { A = xh; W = wq; bias = bq; C = Qh; rowBase = y * 128; }
    else if (y < 48) { A = ch; W = wk; bias = bk; C = Kh; rowBase = (y - 16) * 128; }
    else             { A = ch; W = wv; bias = bv; C = Vh; rowBase = (y - 48) * 128; }
    gemm_body(A, W, bias, nullptr, C, E_, KDIM, rowBase, blockIdx.x * 128, gsm);
}

// Vocab projection (fp32 out).
__global__ __launch_bounds__(GT, 2)
void gemm_vocab(const __half* __restrict__ A, const __half* __restrict__ W,
                const float* __restrict__ bias, float* __restrict__ C)
{
    extern __shared__ __align__(16) char gsm[];
    gemm_body(A, W, bias, C, nullptr, VOC_, KDIM,
              blockIdx.y * 128, blockIdx.x * 128, gsm);
}

// ---------------------------------------------------------------------------
// fp16 flash attention (round-11 version): CTA = (128-q tile, head, batch),
// 128 thr / 4 warps, warp q-tile 32, Q fragments hoisted, 3-stage pipeline.
// ---------------------------------------------------------------------------
#define AS 72   // attention smem row stride in halves (64 + 8 pad = 144B)
#define ATTN_SMEM ((128 * AS + 6 * 64 * AS) * 2)
#define AT 128  // threads per attention CTA

__global__ __launch_bounds__(AT)
void attn_h(const __half* __restrict__ Q, const __half* __restrict__ K,
            const __half* __restrict__ V, __half* __restrict__ O)
{
    extern __shared__ __align__(16) __half sh[];
    __half* Qs = sh;                       // 128*72
    __half* Ks = sh + 128 * AS;            // 3 stages of 64*72
    __half* Vs = Ks + 3 * 64 * AS;         // 3 stages of 64*72

    const int tid = threadIdx.x, lane = tid & 31, wid = tid >> 5;
    const int qt = blockIdx.x, h = blockIdx.y, b = blockIdx.z;

    const __half* Qg = Q + ((size_t)b * SQ_ + qt * 128) * E_ + h * 64;
#pragma unroll
    for (int i = 0; i < 8; i++) {
        int idx = tid + i * AT;            // 0..1023
        int row = idx >> 3, seg = idx & 7;
        *(uint4*)(Qs + row * AS + seg * 8) =
            *(const uint4*)(Qg + (size_t)row * E_ + seg * 8);
    }

    const __half* Kg0 = K + (size_t)b * SKV_ * E_ + h * 64;
    const __half* Vg0 = V + (size_t)b * SKV_ * E_ + h * 64;
    const uint32_t ksb = smem_u32(Ks), vsb = smem_u32(Vs);
    const uint32_t KSTG = 64 * AS * 2;

    auto issue = [&](int st, int c) {
        const __half* Kg = Kg0 + (size_t)c * 64 * E_;
        const __half* Vg = Vg0 + (size_t)c * 64 * E_;
#pragma unroll
        for (int i = 0; i < 4; i++) {
            int idx = tid + i * AT;        // 0..511
            int row = idx >> 3, seg = idx & 7;
            uint32_t so = st * KSTG + (row * AS + seg * 8) * 2;
            CP16(ksb + so, Kg + (size_t)row * E_ + seg * 8);
            CP16(vsb + so, Vg + (size_t)row * E_ + seg * 8);
        }
        CP_COMMIT();
    };

    issue(0, 0);
    issue(1, 1);
    __syncthreads();                        // Q smem visible to all warps

    // Hoist Q fragments: warp owns q rows wid*32 .. wid*32+31 (2 m-tiles)
    uint32_t qf[4][2][4];                   // [ks][mt]
    {
        const uint32_t qA = smem_u32(Qs + (wid * 32 + (lane & 15)) * AS + (lane >> 4) * 8);
#pragma unroll
        for (int ks = 0; ks < 4; ks++)
#pragma unroll
            for (int mt = 0; mt < 2; mt++)
                LDSM4(qf[ks][mt][0], qf[ks][mt][1], qf[ks][mt][2], qf[ks][mt][3],
                      qA + (mt * 16 * AS + ks * 16) * 2);
    }

    float m2[4] = { -1e30f, -1e30f, -1e30f, -1e30f };
    float ls[4] = { 0.f, 0.f, 0.f, 0.f };
    float o[2][8][4];
#pragma unroll
    for (int mt = 0; mt < 2; mt++)
#pragma unroll
        for (int i = 0; i < 8; i++)
#pragma unroll
            for (int j = 0; j < 4; j++) o[mt][i][j] = 0.f;

    const float c2 = 0.125f * 1.44269504089f;   // scale * log2(e)
    const int NKV = SKV_ / 64;

    int st = 0, st2 = 2;
    for (int c = 0; c < NKV; c++) {
        if (c < NKV - 1) CP_WAIT1(); else CP_WAIT0();
        __syncthreads();
        const uint32_t so = st * KSTG;

        // ---- S = Q @ K^T  (32 x 64 per warp); each K ldmatrix feeds 4 MMAs
        float sacc[2][8][4];
#pragma unroll
        for (int mt = 0; mt < 2; mt++)
#pragma unroll
            for (int i = 0; i < 8; i++)
#pragma unroll
                for (int j = 0; j < 4; j++) sacc[mt][i][j] = 0.f;

#pragma unroll
        for (int ks = 0; ks < 4; ks++)
#pragma unroll
            for (int np = 0; np < 4; np++) {
                uint32_t d0, d1, d2, d3;
                LDSM4(d0, d1, d2, d3,
                      ksb + so + ((np * 16 + (lane & 15)) * AS + ks * 16 + (lane >> 4) * 8) * 2);
                MMA16816(sacc[0][np * 2],     qf[ks][0], d0, d2);
                MMA16816(sacc[0][np * 2 + 1], qf[ks][0], d1, d3);
                MMA16816(sacc[1][np * 2],     qf[ks][1], d0, d2);
                MMA16816(sacc[1][np * 2 + 1], qf[ks][1], d1, d3);
            }

        // ---- online softmax (base-2); 4 row groups: idx = mt*2 + rr
#pragma unroll
        for (int mt = 0; mt < 2; mt++)
#pragma unroll
            for (int i = 0; i < 8; i++)
#pragma unroll
                for (int j = 0; j < 4; j++) sacc[mt][i][j] *= c2;

#pragma unroll
        for (int idx = 0; idx < 4; idx++) {
            const int mt = idx >> 1, rh = idx & 1;
            float mx = -1e30f;
#pragma unroll
            for (int nt = 0; nt < 8; nt++)
                mx = fmaxf(mx, fmaxf(sacc[mt][nt][rh * 2], sacc[mt][nt][rh * 2 + 1]));
            mx = fmaxf(mx, __shfl_xor_sync(0xffffffffu, mx, 1));
            mx = fmaxf(mx, __shfl_xor_sync(0xffffffffu, mx, 2));
            const float mn = fmaxf(m2[idx], mx);
            const float al = exp2f(m2[idx] - mn);
            float rs = 0.f;
#pragma unroll
            for (int nt = 0; nt < 8; nt++) {
                sacc[mt][nt][rh * 2]     = exp2f(sacc[mt][nt][rh * 2]     - mn);
                sacc[mt][nt][rh * 2 + 1] = exp2f(sacc[mt][nt][rh * 2 + 1] - mn);
                rs += sacc[mt][nt][rh * 2] + sacc[mt][nt][rh * 2 + 1];
            }
            rs += __shfl_xor_sync(0xffffffffu, rs, 1);
            rs += __shfl_xor_sync(0xffffffffu, rs, 2);
            ls[idx] = ls[idx] * al + rs;
            m2[idx] = mn;
#pragma unroll
            for (int nt = 0; nt < 8; nt++) {
                o[mt][nt][rh * 2]     *= al;
                o[mt][nt][rh * 2 + 1] *= al;
            }
        }

        // ---- O += P @ V ; each V ldmatrix feeds 4 MMAs
        const int g = lane >> 3;
#pragma unroll
        for (int t = 0; t < 4; t++) {
            uint32_t pa[2][4];
#pragma unroll
            for (int mt = 0; mt < 2; mt++) {
                pa[mt][0] = packh2(sacc[mt][2 * t][0],     sacc[mt][2 * t][1]);
                pa[mt][1] = packh2(sacc[mt][2 * t][2],     sacc[mt][2 * t][3]);
                pa[mt][2] = packh2(sacc[mt][2 * t + 1][0], sacc[mt][2 * t + 1][1]);
                pa[mt][3] = packh2(sacc[mt][2 * t + 1][2], sacc[mt][2 * t + 1][3]);
            }
#pragma unroll
            for (int np = 0; np < 4; np++) {
                uint32_t d0, d1, d2, d3;
                uint32_t va = vsb + so +
                    ((t * 16 + (g & 1) * 8 + (lane & 7)) * AS + np * 16 + (g >> 1) * 8) * 2;
                LDSM4T(d0, d1, d2, d3, va);
                MMA16816(o[0][np * 2],     pa[0], d0, d1);
                MMA16816(o[0][np * 2 + 1], pa[0], d2, d3);
                MMA16816(o[1][np * 2],     pa[1], d0, d1);
                MMA16816(o[1][np * 2 + 1], pa[1], d2, d3);
            }
        }

        if (c + 2 < NKV) issue(st2, c + 2);
        st  = (st  == 2) ? 0 : st  + 1;
        st2 = (st2 == 2) ? 0 : st2 + 1;
    }

    // ---- epilogue: normalize, fp16 store
#pragma unroll
    for (int mt = 0; mt < 2; mt++)
#pragma unroll
        for (int rr = 0; rr < 2; rr++) {
            const float inv = 1.f / ls[mt * 2 + rr];
            const int row = qt * 128 + wid * 32 + mt * 16 + rr * 8 + (lane >> 2);
            const size_t base = ((size_t)b * SQ_ + row) * E_ + h * 64 + (lane & 3) * 2;
#pragma unroll
            for (int nt = 0; nt < 8; nt++)
                *(__half2*)(O + base + nt * 8) =
                    __floats2half2_rn(o[mt][nt][rr * 2] * inv, o[mt][nt][rr * 2 + 1] * inv);
        }
}

// ---------------------------------------------------------------------------
// Launch
// ---------------------------------------------------------------------------
extern "C" void kernel_launch(void* const* d_in, const int* in_sizes, int n_in,
                              void* d_out, int out_size)
{
    (void)in_sizes; (void)n_in; (void)out_size;
    const float* x   = (const float*)d_in[0];
    const float* ctx = (const float*)d_in[1];
    const float* Wq  = (const float*)d_in[2];
    const float* bq  = (const float*)d_in[3];
    const float* Wk  = (const float*)d_in[4];
    const float* bk  = (const float*)d_in[5];
    const float* Wv  = (const float*)d_in[6];
    const float* bv  = (const float*)d_in[7];
    const float* Wp  = (const float*)d_in[8];
    const float* bp  = (const float*)d_in[9];
    float* out = (float*)d_out;

    __half *Qh, *Kh, *Vh, *AOh, *xh, *ch, *wq, *wk, *wv, *wp;
    cudaGetSymbolAddress((void**)&Qh,  g_Qh);
    cudaGetSymbolAddress((void**)&Kh,  g_Kh);
    cudaGetSymbolAddress((void**)&Vh,  g_Vh);
    cudaGetSymbolAddress((void**)&AOh, g_AOh);
    cudaGetSymbolAddress((void**)&xh,  g_xh);
    cudaGetSymbolAddress((void**)&ch,  g_ch);
    cudaGetSymbolAddress((void**)&wq,  g_Wqh);
    cudaGetSymbolAddress((void**)&wk,  g_Wkh);
    cudaGetSymbolAddress((void**)&wv,  g_Wvh);
    cudaGetSymbolAddress((void**)&wp,  g_Wph);

    cudaFuncSetAttribute(attn_h,    cudaFuncAttributeMaxDynamicSharedMemorySize, ATTN_SMEM);
    cudaFuncSetAttribute(gemm_qkv,  cudaFuncAttributeMaxDynamicSharedMemorySize, GEMM_SMEM);
    cudaFuncSetAttribute(gemm_vocab,cudaFuncAttributeMaxDynamicSharedMemorySize, GEMM_SMEM);

    // all fp32 -> fp16 conversions, one launch
    f2h_all<<<F2H_BLOCKS, 256>>>(x, ctx, Wq, Wk, Wv, Wp,
                                 xh, ch, wq, wk, wv, wp);

    // QKV projections, one launch, flattened exact grid (640 CTAs)
    gemm_qkv<<<dim3(E_ / 128, 80), GT, GEMM_SMEM>>>(
        xh, ch, wq, wk, wv, bq, bk, bv, Qh, Kh, Vh);

    // attention (fp16 in/out)
    attn_h<<<dim3(SQ_ / 128, H_, B_), AT, ATTN_SMEM>>>(Qh, Kh, Vh, AOh);

    // vocab projection (fp32 out)
    gemm_vocab<<<dim3(VOC_ / 128, (B_ * SQ_) / 128), GT, GEMM_SMEM>>>(AOh, wp, bp, out);
}

// round 15
// speedup vs baseline: 4.3618x; 1.0049x over previous
#include <cuda_runtime.h>
#include <cuda_fp16.h>
#include <cstdint>

#define B_   2
#define SQ_  1024
#define SKV_ 2048
#define E_   1024
#define H_   16
#define VOC_ 4096
#define KDIM 1024

// ---------------------------------------------------------------------------
// Static scratch
// ---------------------------------------------------------------------------
__device__ __half g_Qh [B_*SQ_ *E_];
__device__ __half g_Kh [B_*SKV_*E_];
__device__ __half g_Vh [B_*SKV_*E_];
__device__ __half g_AOh[B_*SQ_ *E_];
__device__ __half g_xh [B_*SQ_ *E_];
__device__ __half g_ch [B_*SKV_*E_];
__device__ __half g_Wqh[E_*E_];
__device__ __half g_Wkh[E_*E_];
__device__ __half g_Wvh[E_*E_];
__device__ __half g_Wph[(size_t)E_*VOC_];

// ---------------------------------------------------------------------------
// PTX helpers (baseline PTX only — compiles for compute_103)
// ---------------------------------------------------------------------------
__device__ __forceinline__ uint32_t smem_u32(const void* p) {
    uint32_t a;
    asm("{ .reg .u64 t; cvta.to.shared.u64 t, %1; cvt.u32.u64 %0, t; }"
        : "=r"(a) : "l"(p));
    return a;
}

#define CP16(s, g) \
    asm volatile("cp.async.cg.shared.global [%0], [%1], 16;" :: "r"(s), "l"(g))
#define CP_COMMIT() asm volatile("cp.async.commit_group;" ::: "memory")
#define CP_WAIT0()  asm volatile("cp.async.wait_group 0;" ::: "memory")
#define CP_WAIT1()  asm volatile("cp.async.wait_group 1;" ::: "memory")

#define LDSM4(d0, d1, d2, d3, a)                                              \
    asm volatile("ldmatrix.sync.aligned.m8n8.x4.shared.b16 {%0,%1,%2,%3}, [%4];" \
        : "=r"(d0), "=r"(d1), "=r"(d2), "=r"(d3) : "r"(a))
#define LDSM4T(d0, d1, d2, d3, a)                                             \
    asm volatile("ldmatrix.sync.aligned.m8n8.x4.trans.shared.b16 {%0,%1,%2,%3}, [%4];" \
        : "=r"(d0), "=r"(d1), "=r"(d2), "=r"(d3) : "r"(a))

#define MMA16816(c, a, b0, b1)                                                \
    asm volatile("mma.sync.aligned.m16n8k16.row.col.f32.f16.f16.f32 "         \
        "{%0,%1,%2,%3},{%4,%5,%6,%7},{%8,%9},{%0,%1,%2,%3};"                  \
        : "+f"((c)[0]), "+f"((c)[1]), "+f"((c)[2]), "+f"((c)[3])              \
        : "r"((a)[0]), "r"((a)[1]), "r"((a)[2]), "r"((a)[3]), "r"(b0), "r"(b1))

// pack two f32 into f16x2: lo = first arg, hi = second arg
#define PACK2(d, lo, hi) \
    asm("cvt.rn.f16x2.f32 %0, %1, %2;" : "=r"(d) : "f"(hi), "f"(lo))
// ex2 on both halves of an f16x2
#define H2EXP2(d, s) \
    asm("ex2.approx.f16x2 %0, %1;" : "=r"(d) : "r"(s))

// ---------------------------------------------------------------------------
// Fused fp32 -> fp16 conversion for ALL tensors in ONE launch.
// ---------------------------------------------------------------------------
#define F2H_BLOCKS 13312

__global__ __launch_bounds__(256)
void f2h_all(const float* __restrict__ x,   const float* __restrict__ ctx,
             const float* __restrict__ wq,  const float* __restrict__ wk,
             const float* __restrict__ wv,  const float* __restrict__ wp,
             __half* xh, __half* ch, __half* wqh,
             __half* wkh, __half* wvh, __half* wph)
{
    const int bb = blockIdx.x;
    const float* in; __half* out; int base;
    if      (bb < 2048) { in = x;   out = xh;  base = bb;        }
    else if (bb < 6144) { in = ctx; out = ch;  base = bb - 2048; }
    else if (bb < 7168) { in = wq;  out = wqh; base = bb - 6144; }
    else if (bb < 8192) { in = wk;  out = wkh; base = bb - 7168; }
    else if (bb < 9216) { in = wv;  out = wvh; base = bb - 8192; }
    else                { in = wp;  out = wph; base = bb - 9216; }
    const size_t i = (size_t)base * 1024 + threadIdx.x * 4;
    float4 v = *(const float4*)(in + i);
    *(__half2*)(out + i)     = __floats2half2_rn(v.x, v.y);
    *(__half2*)(out + i + 2) = __floats2half2_rn(v.z, v.w);
}

// ---------------------------------------------------------------------------
// fp16 tensor-core GEMM body (round-11 structure, + epilogue output scale):
// 128x128x32 CTA tile, 128 threads / 4 warps in 2x2 grid, warp tile 64x64,
// 3-stage cp.async, one sync per K-iteration, compile-time traversal order.
// ---------------------------------------------------------------------------
#define GS   40          // A smem row stride (halves): 32 + 8 pad = 80B
#define BSS  136         // B smem row stride (halves): 128 + 8 pad = 272B
#define A_STG (128 * GS * 2)
#define B_STG (32 * BSS * 2)
#define GEMM_SMEM (3 * (A_STG + B_STG))
#define GT 128           // threads per GEMM CTA

__device__ __forceinline__
void gemm_body(const __half* __restrict__ A, const __half* __restrict__ W,
               const float* __restrict__ bias, float* __restrict__ Cf,
               __half* __restrict__ Ch, int N, int K,
               int rowBase, int colBase, float oscale, char* gsm)
{
    __half* As = (__half*)gsm;
    __half* Bs = (__half*)(gsm + 3 * A_STG);

    const int tid = threadIdx.x;
    const int lane = tid & 31, wid = tid >> 5;
    const int wm = wid & 1, wn = wid >> 1;        // 2x2 warp grid, 64x64 tiles

    const __half* Aga[4]; uint32_t sAa[4];
#pragma unroll
    for (int i = 0; i < 4; i++) {
        const int idx = tid + i * GT;
        const int row = idx >> 2, seg = idx & 3;
        Aga[i] = A + (size_t)(rowBase + row) * K + seg * 8;
        sAa[i] = smem_u32(As + row * GS + seg * 8);
    }
    const __half* Bga[4]; uint32_t sBa[4];
#pragma unroll
    for (int i = 0; i < 4; i++) {
        const int idx = tid + i * GT;
        const int row = idx >> 4, seg = idx & 15;
        Bga[i] = W + (size_t)row * N + colBase + seg * 8;
        sBa[i] = smem_u32(Bs + row * BSS + seg * 8);
    }

    auto issue = [&](int st, int it) {
        const int kk = it * 32;
        const size_t koff = (size_t)kk * N;
#pragma unroll
        for (int i = 0; i < 4; i++) {
            CP16(sAa[i] + st * A_STG, Aga[i] + kk);
            CP16(sBa[i] + st * B_STG, Bga[i] + koff);
        }
        CP_COMMIT();
    };

    const uint32_t aAddr = smem_u32(As + (wm * 64 + (lane & 15)) * GS + (lane >> 4) * 8);
    const int g = lane >> 3;
    const uint32_t bAddr = smem_u32(Bs + ((g & 1) * 8 + (lane & 7)) * BSS
                                       + wn * 64 + (g >> 1) * 8);

    float acc[4][8][4];
#pragma unroll
    for (int i = 0; i < 4; i++)
#pragma unroll
        for (int j = 0; j < 8; j++)
#pragma unroll
            for (int q = 0; q < 4; q++) acc[i][j][q] = 0.f;

    issue(0, 0);
    issue(1, 1);

    const int NIT = K >> 5;
    int st = 0, st2 = 2;
    for (int it = 0; it < NIT; it++) {
        if (it < NIT - 1) CP_WAIT1(); else CP_WAIT0();
        __syncthreads();

        const uint32_t ao = st * A_STG, bo = st * B_STG;
#pragma unroll
        for (int ks = 0; ks < 2; ks++) {
            uint32_t a[4][4];
#pragma unroll
            for (int mt = 0; mt < 4; mt++)
                LDSM4(a[mt][0], a[mt][1], a[mt][2], a[mt][3],
                      aAddr + ao + (mt * 16 * GS + ks * 16) * 2);
#pragma unroll
            for (int np = 0; np < 4; np++) {
                uint32_t d0, d1, d2, d3;
                LDSM4T(d0, d1, d2, d3,
                       bAddr + bo + (ks * 16 * BSS + np * 16) * 2);
#pragma unroll
                for (int mt = 0; mt < 4; mt++) {
                    MMA16816(acc[mt][np * 2],     a[mt], d0, d1);
                    MMA16816(acc[mt][np * 2 + 1], a[mt], d2, d3);
                }
            }
        }

        if (it + 2 < NIT) issue(st2, it + 2);
        st  = (st  == 2) ? 0 : st  + 1;
        st2 = (st2 == 2) ? 0 : st2 + 1;
    }

    const int r0 = rowBase + wm * 64 + (lane >> 2);
    const int c0 = colBase + wn * 64 + (lane & 3) * 2;
#pragma unroll
    for (int mt = 0; mt < 4; mt++)
#pragma unroll
        for (int nt = 0; nt < 8; nt++) {
            const int c = c0 + nt * 8;
            const float bx = bias[c], by = bias[c + 1];
#pragma unroll
            for (int rr = 0; rr < 2; rr++) {
                const int r = r0 + mt * 16 + rr * 8;
                const float vx = (acc[mt][nt][rr * 2]     + bx) * oscale;
                const float vy = (acc[mt][nt][rr * 2 + 1] + by) * oscale;
                if (Cf) {
                    float2 o; o.x = vx; o.y = vy;
                    *(float2*)(Cf + (size_t)r * N + c) = o;
                } else {
                    *(__half2*)(Ch + (size_t)r * N + c) = __floats2half2_rn(vx, vy);
                }
            }
        }
}

// attention scale * log2(e), folded into the Q projection output
#define C2SCALE (0.125f * 1.44269504089f)

// Merged QKV projection, flattened grid: y in [0,80) selects op + row tile.
__global__ __launch_bounds__(GT, 2)
void gemm_qkv(const __half* __restrict__ xh, const __half* __restrict__ ch,
              const __half* __restrict__ wq, const __half* __restrict__ wk,
              const __half* __restrict__ wv,
              const float* __restrict__ bq, const float* __restrict__ bk,
              const float* __restrict__ bv,
              __half* __restrict__ Qh, __half* __restrict__ Kh,
              __half* __restrict__ Vh)
{
    extern __shared__ __align__(16) char gsm[];
    const int y = blockIdx.y;
    const __half* A; const __half* W; const float* bias; __half* C;
    int rowBase; float os;
    if (y < 16)      { A = xh; W = wq; bias = bq; C = Qh; rowBase = y * 128;       os = C2SCALE; }
    else if (y < 48) { A = ch; W = wk; bias = bk; C = Kh; rowBase = (y - 16) * 128; os = 1.0f; }
    else             { A = ch; W = wv; bias = bv; C = Vh; rowBase = (y - 48) * 128; os = 1.0f; }
    gemm_body(A, W, bias, nullptr, C, E_, KDIM, rowBase, blockIdx.x * 128, os, gsm);
}

// Vocab projection (fp32 out).
__global__ __launch_bounds__(GT, 2)
void gemm_vocab(const __half* __restrict__ A, const __half* __restrict__ W,
                const float* __restrict__ bias, float* __restrict__ C)
{
    extern __shared__ __align__(16) char gsm[];
    gemm_body(A, W, bias, C, nullptr, VOC_, KDIM,
              blockIdx.y * 128, blockIdx.x * 128, 1.0f, gsm);
}

// ---------------------------------------------------------------------------
// fp16 flash attention: CTA = (128-q tile, head, batch), 128 thr / 4 warps,
// warp q-tile 32, Q fragments hoisted, 3-stage pipeline.
// Softmax: Q pre-scaled (no c2 mul), fp16 exponentials (ex2.approx.f16x2),
// row sums via P @ ones tensor-core MMA (exact fp32 sums of the fp16 P).
// ---------------------------------------------------------------------------
#define AS 72   // attention smem row stride in halves (64 + 8 pad = 144B)
#define ATTN_SMEM ((128 * AS + 6 * 64 * AS) * 2)
#define AT 128  // threads per attention CTA

__global__ __launch_bounds__(AT)
void attn_h(const __half* __restrict__ Q, const __half* __restrict__ K,
            const __half* __restrict__ V, __half* __restrict__ O)
{
    extern __shared__ __align__(16) __half sh[];
    __half* Qs = sh;                       // 128*72
    __half* Ks = sh + 128 * AS;            // 3 stages of 64*72
    __half* Vs = Ks + 3 * 64 * AS;         // 3 stages of 64*72

    const int tid = threadIdx.x, lane = tid & 31, wid = tid >> 5;
    const int qt = blockIdx.x, h = blockIdx.y, b = blockIdx.z;

    const __half* Qg = Q + ((size_t)b * SQ_ + qt * 128) * E_ + h * 64;
#pragma unroll
    for (int i = 0; i < 8; i++) {
        int idx = tid + i * AT;            // 0..1023
        int row = idx >> 3, seg = idx & 7;
        *(uint4*)(Qs + row * AS + seg * 8) =
            *(const uint4*)(Qg + (size_t)row * E_ + seg * 8);
    }

    const __half* Kg0 = K + (size_t)b * SKV_ * E_ + h * 64;
    const __half* Vg0 = V + (size_t)b * SKV_ * E_ + h * 64;
    const uint32_t ksb = smem_u32(Ks), vsb = smem_u32(Vs);
    const uint32_t KSTG = 64 * AS * 2;

    auto issue = [&](int st, int c) {
        const __half* Kg = Kg0 + (size_t)c * 64 * E_;
        const __half* Vg = Vg0 + (size_t)c * 64 * E_;
#pragma unroll
        for (int i = 0; i < 4; i++) {
            int idx = tid + i * AT;        // 0..511
            int row = idx >> 3, seg = idx & 7;
            uint32_t so = st * KSTG + (row * AS + seg * 8) * 2;
            CP16(ksb + so, Kg + (size_t)row * E_ + seg * 8);
            CP16(vsb + so, Vg + (size_t)row * E_ + seg * 8);
        }
        CP_COMMIT();
    };

    issue(0, 0);
    issue(1, 1);
    __syncthreads();                        // Q smem visible to all warps

    // Hoist Q fragments: warp owns q rows wid*32 .. wid*32+31 (2 m-tiles)
    uint32_t qf[4][2][4];                   // [ks][mt]
    {
        const uint32_t qA = smem_u32(Qs + (wid * 32 + (lane & 15)) * AS + (lane >> 4) * 8);
#pragma unroll
        for (int ks = 0; ks < 4; ks++)
#pragma unroll
            for (int mt = 0; mt < 2; mt++)
                LDSM4(qf[ks][mt][0], qf[ks][mt][1], qf[ks][mt][2], qf[ks][mt][3],
                      qA + (mt * 16 * AS + ks * 16) * 2);
    }

    float m2[4] = { -1e30f, -1e30f, -1e30f, -1e30f };
    float ls[4] = { 0.f, 0.f, 0.f, 0.f };
    float o[2][8][4];
#pragma unroll
    for (int mt = 0; mt < 2; mt++)
#pragma unroll
        for (int i = 0; i < 8; i++)
#pragma unroll
            for (int j = 0; j < 4; j++) o[mt][i][j] = 0.f;

    const uint32_t ONES = 0x3C003C00u;      // fp16 1.0 x2
    const int NKV = SKV_ / 64;

    int st = 0, st2 = 2;
    for (int c = 0; c < NKV; c++) {
        if (c < NKV - 1) CP_WAIT1(); else CP_WAIT0();
        __syncthreads();
        const uint32_t so = st * KSTG;

        // ---- S = Q @ K^T  (scores arrive pre-scaled by c2 via Q)
        float sacc[2][8][4];
#pragma unroll
        for (int mt = 0; mt < 2; mt++)
#pragma unroll
            for (int i = 0; i < 8; i++)
#pragma unroll
                for (int j = 0; j < 4; j++) sacc[mt][i][j] = 0.f;

#pragma unroll
        for (int ks = 0; ks < 4; ks++)
#pragma unroll
            for (int np = 0; np < 4; np++) {
                uint32_t d0, d1, d2, d3;
                LDSM4(d0, d1, d2, d3,
                      ksb + so + ((np * 16 + (lane & 15)) * AS + ks * 16 + (lane >> 4) * 8) * 2);
                MMA16816(sacc[0][np * 2],     qf[ks][0], d0, d2);
                MMA16816(sacc[0][np * 2 + 1], qf[ks][0], d1, d3);
                MMA16816(sacc[1][np * 2],     qf[ks][1], d0, d2);
                MMA16816(sacc[1][np * 2 + 1], qf[ks][1], d1, d3);
            }

        // ---- max update + subtract (per row group idx = mt*2 + rh)
        float al4[4];
#pragma unroll
        for (int idx = 0; idx < 4; idx++) {
            const int mt = idx >> 1, rh = idx & 1;
            float mx = -1e30f;
#pragma unroll
            for (int nt = 0; nt < 8; nt++)
                mx = fmaxf(mx, fmaxf(sacc[mt][nt][rh * 2], sacc[mt][nt][rh * 2 + 1]));
            mx = fmaxf(mx, __shfl_xor_sync(0xffffffffu, mx, 1));
            mx = fmaxf(mx, __shfl_xor_sync(0xffffffffu, mx, 2));
            const float mn = fmaxf(m2[idx], mx);
            al4[idx] = exp2f(m2[idx] - mn);
            m2[idx] = mn;
#pragma unroll
            for (int nt = 0; nt < 8; nt++) {
                sacc[mt][nt][rh * 2]     -= mn;
                sacc[mt][nt][rh * 2 + 1] -= mn;
            }
        }

        // ---- P = exp2 in fp16, packed directly as MMA A-fragments
        uint32_t ph[4][2][4];               // [t][mt][frag]
#pragma unroll
        for (int t = 0; t < 4; t++)
#pragma unroll
            for (int mt = 0; mt < 2; mt++) {
                uint32_t p0, p1, p2, p3;
                PACK2(p0, sacc[mt][2 * t][0],     sacc[mt][2 * t][1]);
                PACK2(p1, sacc[mt][2 * t][2],     sacc[mt][2 * t][3]);
                PACK2(p2, sacc[mt][2 * t + 1][0], sacc[mt][2 * t + 1][1]);
                PACK2(p3, sacc[mt][2 * t + 1][2], sacc[mt][2 * t + 1][3]);
                H2EXP2(ph[t][mt][0], p0);
                H2EXP2(ph[t][mt][1], p1);
                H2EXP2(ph[t][mt][2], p2);
                H2EXP2(ph[t][mt][3], p3);
            }

        // ---- row sums via P @ ones (exact fp32 sums of the fp16 P)
        float rsacc[2][4];
#pragma unroll
        for (int mt = 0; mt < 2; mt++)
#pragma unroll
            for (int j = 0; j < 4; j++) rsacc[mt][j] = 0.f;
#pragma unroll
        for (int t = 0; t < 4; t++) {
            MMA16816(rsacc[0], ph[t][0], ONES, ONES);
            MMA16816(rsacc[1], ph[t][1], ONES, ONES);
        }

        // ---- ls / o rescale
#pragma unroll
        for (int idx = 0; idx < 4; idx++) {
            const int mt = idx >> 1, rh = idx & 1;
            ls[idx] = ls[idx] * al4[idx] + rsacc[mt][rh * 2];
#pragma unroll
            for (int nt = 0; nt < 8; nt++) {
                o[mt][nt][rh * 2]     *= al4[idx];
                o[mt][nt][rh * 2 + 1] *= al4[idx];
            }
        }

        // ---- O += P @ V
        const int g = lane >> 3;
#pragma unroll
        for (int t = 0; t < 4; t++) {
#pragma unroll
            for (int np = 0; np < 4; np++) {
                uint32_t d0, d1, d2, d3;
                uint32_t va = vsb + so +
                    ((t * 16 + (g & 1) * 8 + (lane & 7)) * AS + np * 16 + (g >> 1) * 8) * 2;
                LDSM4T(d0, d1, d2, d3, va);
                MMA16816(o[0][np * 2],     ph[t][0], d0, d1);
                MMA16816(o[0][np * 2 + 1], ph[t][0], d2, d3);
                MMA16816(o[1][np * 2],     ph[t][1], d0, d1);
                MMA16816(o[1][np * 2 + 1], ph[t][1], d2, d3);
            }
        }

        if (c + 2 < NKV) issue(st2, c + 2);
        st  = (st  == 2) ? 0 : st  + 1;
        st2 = (st2 == 2) ? 0 : st2 + 1;
    }

    // ---- epilogue: normalize, fp16 store
#pragma unroll
    for (int mt = 0; mt < 2; mt++)
#pragma unroll
        for (int rr = 0; rr < 2; rr++) {
            const float inv = 1.f / ls[mt * 2 + rr];
            const int row = qt * 128 + wid * 32 + mt * 16 + rr * 8 + (lane >> 2);
            const size_t base = ((size_t)b * SQ_ + row) * E_ + h * 64 + (lane & 3) * 2;
#pragma unroll
            for (int nt = 0; nt < 8; nt++)
                *(__half2*)(O + base + nt * 8) =
                    __floats2half2_rn(o[mt][nt][rr * 2] * inv, o[mt][nt][rr * 2 + 1] * inv);
        }
}

// ---------------------------------------------------------------------------
// Launch
// ---------------------------------------------------------------------------
extern "C" void kernel_launch(void* const* d_in, const int* in_sizes, int n_in,
                              void* d_out, int out_size)
{
    (void)in_sizes; (void)n_in; (void)out_size;
    const float* x   = (const float*)d_in[0];
    const float* ctx = (const float*)d_in[1];
    const float* Wq  = (const float*)d_in[2];
    const float* bq  = (const float*)d_in[3];
    const float* Wk  = (const float*)d_in[4];
    const float* bk  = (const float*)d_in[5];
    const float* Wv  = (const float*)d_in[6];
    const float* bv  = (const float*)d_in[7];
    const float* Wp  = (const float*)d_in[8];
    const float* bp  = (const float*)d_in[9];
    float* out = (float*)d_out;

    __half *Qh, *Kh, *Vh, *AOh, *xh, *ch, *wq, *wk, *wv, *wp;
    cudaGetSymbolAddress((void**)&Qh,  g_Qh);
    cudaGetSymbolAddress((void**)&Kh,  g_Kh);
    cudaGetSymbolAddress((void**)&Vh,  g_Vh);
    cudaGetSymbolAddress((void**)&AOh, g_AOh);
    cudaGetSymbolAddress((void**)&xh,  g_xh);
    cudaGetSymbolAddress((void**)&ch,  g_ch);
    cudaGetSymbolAddress((void**)&wq,  g_Wqh);
    cudaGetSymbolAddress((void**)&wk,  g_Wkh);
    cudaGetSymbolAddress((void**)&wv,  g_Wvh);
    cudaGetSymbolAddress((void**)&wp,  g_Wph);

    cudaFuncSetAttribute(attn_h,    cudaFuncAttributeMaxDynamicSharedMemorySize, ATTN_SMEM);
    cudaFuncSetAttribute(gemm_qkv,  cudaFuncAttributeMaxDynamicSharedMemorySize, GEMM_SMEM);
    cudaFuncSetAttribute(gemm_vocab,cudaFuncAttributeMaxDynamicSharedMemorySize, GEMM_SMEM);

    // all fp32 -> fp16 conversions, one launch
    f2h_all<<<F2H_BLOCKS, 256>>>(x, ctx, Wq, Wk, Wv, Wp,
                                 xh, ch, wq, wk, wv, wp);

    // QKV projections, one launch, flattened exact grid (640 CTAs)
    gemm_qkv<<<dim3(E_ / 128, 80), GT, GEMM_SMEM>>>(
        xh, ch, wq, wk, wv, bq, bk, bv, Qh, Kh, Vh);

    // attention (fp16 in/out)
    attn_h<<<dim3(SQ_ / 128, H_, B_), AT, ATTN_SMEM>>>(Qh, Kh, Vh, AOh);

    // vocab projection (fp32 out)
    gemm_vocab<<<dim3(VOC_ / 128, (B_ * SQ_) / 128), GT, GEMM_SMEM>>>(AOh, wp, bp, out);
}